// round 2
// baseline (speedup 1.0000x reference)
#include <cuda_runtime.h>
#include <cstdint>
#include <cstddef>

// ---------------------------------------------------------------------------
// AttentionRefinementModule fused pipeline
//   K0 prep:    zero stat accumulators, count unmasked pixels
//   K1 cumsum:  exclusive cumsum over t, write (b,t,ch,l) scratch
//   K2 conv:    5x5 conv (16->32) + bias + relu + mask + 1x1 proj (32->8),
//               writes pre-BN cov into d_out in final (b,n,t,l) layout,
//               accumulates per-channel sum / sumsq
//   K3 stats:   mean/var -> scale/shift per channel
//   K4 apply:   elementwise BN affine on unmasked positions
//
// mask (key_padding_mask) is a bool in the reference; the harness widens it
// to a 4-byte type. We read 32-bit words and treat nonzero as "padded",
// which is correct for both int32 {0,1} and float32 {0.0,1.0} encodings.
// ---------------------------------------------------------------------------

#define B_    8
#define T_    128
#define NH_   8
#define CIN_  16
#define COUT_ 32
#define H_    32
#define W_    64
#define L_    2048   // H_*W_

// scratch: cumsum output, layout ((b*T_+t)*CIN_ + ch)*L_ + l
__device__ float g_cum[(size_t)B_ * T_ * CIN_ * L_];   // 128 MB
__device__ float g_acc[16];      // [0..7] sum, [8..15] sumsq
__device__ float g_cnt;
__device__ float g_scale[8];
__device__ float g_shift[8];

// ---- f32x2 helpers (Blackwell packed fp32) --------------------------------
__device__ __forceinline__ unsigned long long dup2(float v) {
    unsigned long long r;
    asm("mov.b64 %0, {%1, %1};" : "=l"(r) : "f"(v));
    return r;
}
__device__ __forceinline__ unsigned long long fma2(unsigned long long a,
                                                   unsigned long long b,
                                                   unsigned long long c) {
    unsigned long long d;
    asm("fma.rn.f32x2 %0, %1, %2, %3;" : "=l"(d) : "l"(a), "l"(b), "l"(c));
    return d;
}
__device__ __forceinline__ float2 unpk(unsigned long long v) {
    float2 f;
    asm("mov.b64 {%0, %1}, %2;" : "=f"(f.x), "=f"(f.y) : "l"(v));
    return f;
}

// ---------------------------------------------------------------------------
// K0: zero accumulators + count unmasked (b,l) entries (mask = int32 words)
// ---------------------------------------------------------------------------
__global__ void prep_kernel(const int* __restrict__ mask) {
    __shared__ int scnt;
    int tid = threadIdx.x;
    if (tid == 0) scnt = 0;
    if (tid < 16) g_acc[tid] = 0.0f;
    __syncthreads();
    int c = 0;
    for (int i = tid; i < B_ * L_; i += 256) c += (mask[i] == 0);
    #pragma unroll
    for (int off = 16; off; off >>= 1) c += __shfl_xor_sync(0xffffffffu, c, off);
    if ((tid & 31) == 0) atomicAdd(&scnt, c);
    __syncthreads();
    if (tid == 0) g_cnt = fmaxf(128.0f * (float)scnt, 1.0f);
}

// ---------------------------------------------------------------------------
// K1: exclusive cumsum over t. One thread per (b, ch, 4 lanes of l).
// ---------------------------------------------------------------------------
__global__ void cumsum_kernel(const float* __restrict__ prev,
                              const float* __restrict__ curr) {
    int tid = blockIdx.x * blockDim.x + threadIdx.x;   // 0 .. 65535
    int b   = tid >> 13;            // 16 * 512 per b
    int r   = tid & 8191;
    int ch  = r >> 9;
    int l4  = r & 511;

    const float* src0 = (ch < 8)
        ? prev + (size_t)(b * 8 + ch) * T_ * L_
        : curr + (size_t)(b * 8 + (ch - 8)) * T_ * L_;
    const float4* src = reinterpret_cast<const float4*>(src0) + l4;
    float4* dst = reinterpret_cast<float4*>(
        g_cum + ((size_t)(b * T_) * CIN_ + ch) * L_) + l4;

    float4 run = make_float4(0.f, 0.f, 0.f, 0.f);
    float4 nxt = src[0];
    for (int t = 0; t < T_; t++) {
        float4 cur = nxt;
        if (t < T_ - 1) nxt = src[(size_t)(t + 1) * (L_ / 4)];
        dst[(size_t)t * (CIN_ * L_ / 4)] = run;
        run.x += cur.x; run.y += cur.y; run.z += cur.z; run.w += cur.w;
    }
}

// ---------------------------------------------------------------------------
// K2: conv + relu + mask + proj + stat accumulation
// one block per (b,t) image, 256 threads
// smem: padded input [16][36][72], weights [ic][ky][kx][oc], proj, bias, mask
// ---------------------------------------------------------------------------
#define SIN_FLOATS   (CIN_ * 36 * 72)          // 41472
#define SW_FLOATS    (CIN_ * 5 * 5 * COUT_)    // 12800
#define SMEM_FLOATS  (SIN_FLOATS + SW_FLOATS + 256 + 32 + 16)
#define SMEM_BYTES   (SMEM_FLOATS * 4 + L_)    // + mask bytes

__global__ void __launch_bounds__(256, 1)
conv_kernel(const float* __restrict__ convw,
            const float* __restrict__ convb,
            const float* __restrict__ projw,
            const int* __restrict__ mask,
            float* __restrict__ out) {
    extern __shared__ float sm[];
    float* sIn   = sm;
    float* sW    = sm + SIN_FLOATS;
    float* sProj = sW + SW_FLOATS;
    float* sBias = sProj + 256;
    float* sRed  = sBias + 32;
    unsigned char* sMask = reinterpret_cast<unsigned char*>(sRed + 16);

    int tid = threadIdx.x;
    int bt  = blockIdx.x;
    int b   = bt >> 7;
    int t   = bt & 127;

    // init: zero padded input + reduction slots; stage weights (rearranged),
    // bias, proj, mask (word -> byte)
    for (int j = tid; j < SIN_FLOATS; j += 256) sIn[j] = 0.0f;
    if (tid < 16) sRed[tid] = 0.0f;
    for (int j = tid; j < SW_FLOATS; j += 256) {
        int oc = j / 400;
        int r  = j - oc * 400;
        int ic = r / 25;
        int r2 = r - ic * 25;
        int ky = r2 / 5;
        int kx = r2 - ky * 5;
        sW[((ic * 5 + ky) * 5 + kx) * 32 + oc] = convw[j];
    }
    if (tid < 32) sBias[tid] = convb[tid];
    if (tid < 256) sProj[tid] = projw[tid];
    for (int j = tid; j < L_; j += 256)
        sMask[j] = (mask[b * L_ + j] != 0) ? 1 : 0;
    __syncthreads();

    // fill interior of padded input from cumsum scratch
    const float4* in4 = reinterpret_cast<const float4*>(
        g_cum + (size_t)bt * CIN_ * L_);
    for (int j = tid; j < CIN_ * L_ / 4; j += 256) {
        float4 v = in4[j];
        int ic  = j >> 9;
        int pix = (j & 511) << 2;
        int y   = pix >> 6;
        int x   = pix & 63;
        float* dp = sIn + (ic * 36 + y + 2) * 72 + x + 2;
        dp[0] = v.x; dp[1] = v.y; dp[2] = v.z; dp[3] = v.w;
    }
    __syncthreads();

    float ls[8], lsq[8];
    #pragma unroll
    for (int n = 0; n < 8; n++) { ls[n] = 0.f; lsq[n] = 0.f; }

    for (int tile = 0; tile < 4; tile++) {
        int p0 = tile * 512 + tid * 2;
        int y  = p0 >> 6;
        int x  = p0 & 63;

        unsigned long long acc[16][2];
        #pragma unroll
        for (int i = 0; i < 16; i++) { acc[i][0] = 0ull; acc[i][1] = 0ull; }

        #pragma unroll 1
        for (int ic = 0; ic < CIN_; ic++) {
            #pragma unroll
            for (int ky = 0; ky < 5; ky++) {
                const float* irow = sIn + (ic * 36 + y + ky) * 72 + x;
                unsigned long long d[6];
                #pragma unroll
                for (int j = 0; j < 6; j++) d[j] = dup2(irow[j]);
                const float* wbase = sW + (ic * 5 + ky) * 5 * 32;
                #pragma unroll
                for (int kx = 0; kx < 5; kx++) {
                    const ulonglong2* wp =
                        reinterpret_cast<const ulonglong2*>(wbase + kx * 32);
                    #pragma unroll
                    for (int q = 0; q < 8; q++) {
                        ulonglong2 wv = wp[q];
                        acc[2*q  ][0] = fma2(d[kx],     wv.x, acc[2*q  ][0]);
                        acc[2*q  ][1] = fma2(d[kx + 1], wv.x, acc[2*q  ][1]);
                        acc[2*q+1][0] = fma2(d[kx],     wv.y, acc[2*q+1][0]);
                        acc[2*q+1][1] = fma2(d[kx + 1], wv.y, acc[2*q+1][1]);
                    }
                }
            }
        }

        // epilogue: bias + relu + mask + 1x1 proj + stats
        float vv[2][8];
        #pragma unroll
        for (int px = 0; px < 2; px++) {
            float* v = vv[px];
            #pragma unroll
            for (int n = 0; n < 8; n++) v[n] = 0.f;
            if (!sMask[p0 + px]) {
                #pragma unroll
                for (int pi = 0; pi < 16; pi++) {
                    float2 f = unpk(acc[pi][px]);
                    float c0 = fmaxf(f.x + sBias[2 * pi],     0.f);
                    float c1 = fmaxf(f.y + sBias[2 * pi + 1], 0.f);
                    #pragma unroll
                    for (int n = 0; n < 8; n++) {
                        float2 w2 = reinterpret_cast<const float2*>(
                            sProj + n * 32)[pi];
                        v[n] += w2.x * c0 + w2.y * c1;
                    }
                }
            }
            #pragma unroll
            for (int n = 0; n < 8; n++) {
                ls[n] += v[n];
                lsq[n] = fmaf(v[n], v[n], lsq[n]);
            }
        }
        // store pre-BN cov in final (b,n,t,l) layout
        #pragma unroll
        for (int n = 0; n < 8; n++) {
            float2 o = make_float2(vv[0][n], vv[1][n]);
            size_t off = (((size_t)(b * 8 + n) * T_ + t) << 11) + p0;
            *reinterpret_cast<float2*>(out + off) = o;
        }
    }

    // block-level stat reduction -> global atomics
    int lane = tid & 31;
    #pragma unroll
    for (int k = 0; k < 16; k++) {
        float v = (k < 8) ? ls[k] : lsq[k - 8];
        #pragma unroll
        for (int off = 16; off; off >>= 1)
            v += __shfl_xor_sync(0xffffffffu, v, off);
        if (lane == 0) atomicAdd(&sRed[k], v);
    }
    __syncthreads();
    if (tid < 16) atomicAdd(&g_acc[tid], sRed[tid]);
}

// ---------------------------------------------------------------------------
// K3: finalize stats
// ---------------------------------------------------------------------------
__global__ void stats_kernel(const float* __restrict__ gamma,
                             const float* __restrict__ beta) {
    int n = threadIdx.x;
    if (n < 8) {
        float cnt  = g_cnt;
        float mean = g_acc[n] / cnt;
        float var  = g_acc[8 + n] / cnt - mean * mean;
        var = fmaxf(var, 0.0f);
        float inv = rsqrtf(var + 1e-5f);
        float sc  = gamma[n] * inv;
        g_scale[n] = sc;
        g_shift[n] = beta[n] - mean * sc;
    }
}

// ---------------------------------------------------------------------------
// K4: elementwise BN affine (masked positions keep their stored 0)
// ---------------------------------------------------------------------------
__global__ void bn_apply_kernel(float* __restrict__ out,
                                const int* __restrict__ mask) {
    int idx = blockIdx.x * 256 + threadIdx.x;      // float4 index
    int nlin = idx >> 16;                          // 65536 float4 per (b,n)
    int n = nlin & 7;
    int b = nlin >> 3;
    int l4 = idx & 511;
    int4 m = *reinterpret_cast<const int4*>(mask + b * L_ + l4 * 4);
    float4* p = reinterpret_cast<float4*>(out) + idx;
    float4 v = *p;
    float sc = g_scale[n], sh = g_shift[n];
    v.x = m.x ? v.x : fmaf(v.x, sc, sh);
    v.y = m.y ? v.y : fmaf(v.y, sc, sh);
    v.z = m.z ? v.z : fmaf(v.z, sc, sh);
    v.w = m.w ? v.w : fmaf(v.w, sc, sh);
    *p = v;
}

// ---------------------------------------------------------------------------
extern "C" void kernel_launch(void* const* d_in, const int* in_sizes, int n_in,
                              void* d_out, int out_size) {
    const float* prev  = (const float*)d_in[0];
    const float* curr  = (const float*)d_in[1];
    const int*   mask  = (const int*)d_in[2];
    // d_in[3] = h (unused; compile-time constant)
    const float* convw = (const float*)d_in[4];
    const float* convb = (const float*)d_in[5];
    const float* projw = (const float*)d_in[6];
    const float* gamma = (const float*)d_in[7];
    const float* beta  = (const float*)d_in[8];
    float* out = (float*)d_out;

    cudaFuncSetAttribute(conv_kernel,
                         cudaFuncAttributeMaxDynamicSharedMemorySize,
                         SMEM_BYTES);

    prep_kernel<<<1, 256>>>(mask);
    cumsum_kernel<<<256, 256>>>(prev, curr);
    conv_kernel<<<B_ * T_, 256, SMEM_BYTES>>>(convw, convb, projw, mask, out);
    stats_kernel<<<1, 32>>>(gamma, beta);
    bn_apply_kernel<<<(B_ * NH_ * T_ * L_ / 4) / 256, 256>>>(out, mask);
}

// round 6
// speedup vs baseline: 1.4144x; 1.4144x over previous
#include <cuda_runtime.h>
#include <cuda_bf16.h>
#include <cstdint>
#include <cstddef>

// ---------------------------------------------------------------------------
// AttentionRefinementModule — legacy-tensor-core (mma.sync bf16) pipeline.
// Harness ptxas target is plain sm_100 (no 'a'): tcgen05 unavailable, so the
// conv uses mma.sync.m16n8k16 bf16 (HMMA) with 3-term hi/lo splitting and
// register-resident fp32 accumulators.
//   K0 prep:    zero stat accumulators, count unmasked pixels
//   Kw wprep:   split conv weights into bf16 hi/lo planes, [tap][oc][ic]
//   K1 cumsum:  exclusive cumsum over t -> g_cum [bt][ch][px] fp32
//   K2 conv:    implicit GEMM, 5x5 conv + bias + relu + mask + 1x1 proj +
//               stats, pre-BN output in final layout
//   K3 stats:   mean/var -> scale/shift
//   K4 apply:   BN affine on unmasked positions
// ---------------------------------------------------------------------------

#define B_    8
#define T_    128
#define NH_   8
#define CIN_  16
#define COUT_ 32
#define H_    32
#define W_    64
#define L_    2048
#define PW_   68            // padded width (x pad 2 each side)
#define PH_   36            // padded rows  (y pad 2 each side)

__device__ float g_cum[(size_t)B_ * T_ * CIN_ * L_];   // 128 MB scratch
__device__ __nv_bfloat16 g_wp[2 * 25 * COUT_ * CIN_];  // hi/lo weight planes
__device__ float g_acc[16];
__device__ float g_cnt;
__device__ float g_scale[8];
__device__ float g_shift[8];

// ---- smem layout (bytes) --------------------------------------------------
#define OFF_RED   16       // 16 floats
#define OFF_BIAS  80       // 32 floats
#define OFF_PROJ  256      // 256 floats, transposed [oc][n]
#define OFF_MASK  1280     // 2048 bytes
#define OFF_W     3328     // 51200 B: [plane][tap][oc][ic] bf16
#define OFF_AHI   54528    // 128 guard + 2448*32 + 128 tail = 78592 B
#define OFF_ALO   133120
#define SMEM_TOTAL 211712

// ---- PTX helpers ----------------------------------------------------------
__device__ __forceinline__ uint32_t smem_u32(const void* p) {
    uint32_t a;
    asm("{ .reg .u64 t; cvta.to.shared.u64 t, %1; cvt.u32.u64 %0, t; }"
        : "=r"(a) : "l"(p));
    return a;
}
__device__ __forceinline__ void ldsm4(uint32_t* r, uint32_t addr) {
    asm volatile("ldmatrix.sync.aligned.m8n8.x4.shared.b16 {%0,%1,%2,%3}, [%4];"
                 : "=r"(r[0]), "=r"(r[1]), "=r"(r[2]), "=r"(r[3]) : "r"(addr));
}
__device__ __forceinline__ void mma16816(float* c, const uint32_t* a,
                                         const uint32_t* b) {
    asm volatile(
        "mma.sync.aligned.m16n8k16.row.col.f32.bf16.bf16.f32 "
        "{%0,%1,%2,%3}, {%4,%5,%6,%7}, {%8,%9}, {%0,%1,%2,%3};"
        : "+f"(c[0]), "+f"(c[1]), "+f"(c[2]), "+f"(c[3])
        : "r"(a[0]), "r"(a[1]), "r"(a[2]), "r"(a[3]), "r"(b[0]), "r"(b[1]));
}

// ---------------------------------------------------------------------------
// K0 prep
// ---------------------------------------------------------------------------
__global__ void prep_kernel(const int* __restrict__ mask) {
    __shared__ int scnt;
    int tid = threadIdx.x;
    if (tid == 0) scnt = 0;
    if (tid < 16) g_acc[tid] = 0.0f;
    __syncthreads();
    int c = 0;
    for (int i = tid; i < B_ * L_; i += 256) c += (mask[i] == 0);
    #pragma unroll
    for (int off = 16; off; off >>= 1) c += __shfl_xor_sync(0xffffffffu, c, off);
    if ((tid & 31) == 0) atomicAdd(&scnt, c);
    __syncthreads();
    if (tid == 0) g_cnt = fmaxf(128.0f * (float)scnt, 1.0f);
}

// ---------------------------------------------------------------------------
// Kw: weight split hi/lo, layout [plane][tap][oc][ic]
// ---------------------------------------------------------------------------
__global__ void wprep_kernel(const float* __restrict__ convw) {
    int idx = blockIdx.x * 512 + threadIdx.x;
    if (idx >= 12800) return;
    int oc = idx / 400;
    int r  = idx - oc * 400;
    int ic = r / 25;
    int k  = r - ic * 25;            // tap = ky*5+kx
    float w = convw[idx];
    __nv_bfloat16 wh = __float2bfloat16_rn(w);
    __nv_bfloat16 wl = __float2bfloat16_rn(w - __bfloat162float(wh));
    g_wp[(k * 32 + oc) * 16 + ic] = wh;
    g_wp[12800 + (k * 32 + oc) * 16 + ic] = wl;
}

// ---------------------------------------------------------------------------
// K1 cumsum
// ---------------------------------------------------------------------------
__global__ void cumsum_kernel(const float* __restrict__ prev,
                              const float* __restrict__ curr) {
    int tid = blockIdx.x * blockDim.x + threadIdx.x;
    int b   = tid >> 13;
    int r   = tid & 8191;
    int ch  = r >> 9;
    int l4  = r & 511;
    const float* src0 = (ch < 8)
        ? prev + (size_t)(b * 8 + ch) * T_ * L_
        : curr + (size_t)(b * 8 + (ch - 8)) * T_ * L_;
    const float4* src = reinterpret_cast<const float4*>(src0) + l4;
    float4* dst = reinterpret_cast<float4*>(
        g_cum + ((size_t)(b * T_) * CIN_ + ch) * L_) + l4;
    float4 run = make_float4(0.f, 0.f, 0.f, 0.f);
    float4 nxt = src[0];
    for (int t = 0; t < T_; t++) {
        float4 cur = nxt;
        if (t < T_ - 1) nxt = src[(size_t)(t + 1) * (L_ / 4)];
        dst[(size_t)t * (CIN_ * L_ / 4)] = run;
        run.x += cur.x; run.y += cur.y; run.z += cur.z; run.w += cur.w;
    }
}

// ---------------------------------------------------------------------------
// K2 conv via mma.sync bf16 implicit GEMM
// Ext pixel grid: q in [0,2176), q = oy*68+ox+2 for valid outputs.
// A row for (q, ky, kx) lives at plane + 128 + (q + ky*68 + kx - 2)*32.
// ---------------------------------------------------------------------------
__global__ void __launch_bounds__(256)
conv_kernel(const float* __restrict__ convb,
            const float* __restrict__ projw,
            const int* __restrict__ mask,
            float* __restrict__ out) {
    extern __shared__ char sm[];
    uint32_t sb = smem_u32(sm);
    int tid = threadIdx.x;
    int wid = tid >> 5;
    int lane = tid & 31;
    int bt = blockIdx.x;
    int b  = bt >> 7;
    int t  = bt & 127;

    float* sRed   = reinterpret_cast<float*>(sm + OFF_RED);
    float* sBias  = reinterpret_cast<float*>(sm + OFF_BIAS);
    float* sProjT = reinterpret_cast<float*>(sm + OFF_PROJ);
    unsigned char* sMask = reinterpret_cast<unsigned char*>(sm + OFF_MASK);

    // ---- staging ----------------------------------------------------------
    int4 z4 = make_int4(0, 0, 0, 0);
    int4* planes = reinterpret_cast<int4*>(sm + OFF_AHI);
    for (int j = tid; j < (2 * 78592) / 16; j += 256) planes[j] = z4;
    {
        const int4* src = reinterpret_cast<const int4*>(g_wp);
        int4* dst = reinterpret_cast<int4*>(sm + OFF_W);
        for (int j = tid; j < 3200; j += 256) dst[j] = src[j];
    }
    if (tid < 16) sRed[tid] = 0.0f;
    if (tid < 32) sBias[tid] = convb[tid];
    { // transpose proj to [oc][n]
        int n = tid >> 5, oc = tid & 31;
        sProjT[oc * 8 + n] = projw[tid];
    }
    for (int j = tid; j < L_; j += 256)
        sMask[j] = (mask[b * L_ + j] != 0) ? 1 : 0;
    __syncthreads();

    // fp32 [ch][px] -> bf16 hi/lo channel-last padded image
    {
        const float* src = g_cum + (size_t)bt * CIN_ * L_;
        for (int it = 0; it < 8; it++) {
            int px = tid + it * 256;
            uint32_t h[8], l[8];
            #pragma unroll
            for (int cp = 0; cp < 8; cp++) {
                float v0 = src[(2 * cp) * L_ + px];
                float v1 = src[(2 * cp + 1) * L_ + px];
                __nv_bfloat16 h0 = __float2bfloat16_rn(v0);
                __nv_bfloat16 h1 = __float2bfloat16_rn(v1);
                __nv_bfloat16 l0 = __float2bfloat16_rn(v0 - __bfloat162float(h0));
                __nv_bfloat16 l1 = __float2bfloat16_rn(v1 - __bfloat162float(h1));
                h[cp] = ((uint32_t)*reinterpret_cast<uint16_t*>(&h1) << 16)
                      | (uint32_t)*reinterpret_cast<uint16_t*>(&h0);
                l[cp] = ((uint32_t)*reinterpret_cast<uint16_t*>(&l1) << 16)
                      | (uint32_t)*reinterpret_cast<uint16_t*>(&l0);
            }
            int y = px >> 6, x = px & 63;
            int byteoff = 128 + ((y + 2) * PW_ + x + 2) * 32;
            uint4* dh = reinterpret_cast<uint4*>(sm + OFF_AHI + byteoff);
            uint4* dl = reinterpret_cast<uint4*>(sm + OFF_ALO + byteoff);
            dh[0] = make_uint4(h[0], h[1], h[2], h[3]);
            dh[1] = make_uint4(h[4], h[5], h[6], h[7]);
            dl[0] = make_uint4(l[0], l[1], l[2], l[3]);
            dl[1] = make_uint4(l[4], l[5], l[6], l[7]);
        }
    }
    __syncthreads();

    // ---- per-thread ldmatrix base addresses -------------------------------
    // A (x4, non-trans): rows = m (ext pixel), 32B/row; mats {m0-7/k0-7,
    // m8-15/k0-7, m0-7/k8-15, m8-15/k8-15} -> a0..a3
    uint32_t aHiBase = sb + OFF_AHI + 128 - 64
                     + (uint32_t)(lane & 15) * 32 + (uint32_t)(lane >> 4) * 16;
    uint32_t aLoBase = aHiBase + (OFF_ALO - OFF_AHI);
    // B (x4, NON-trans of [oc][ic] rows): mats {oc0-7/ic0-7, oc0-7/ic8-15,
    // oc8-15/ic0-7, oc8-15/ic8-15} -> {b0,b1} oc-octet0, {b0,b1} oc-octet1
    uint32_t wBase = sb + OFF_W
                   + (uint32_t)((lane & 7) + ((lane >> 4) << 3)) * 32
                   + (uint32_t)((lane >> 3) & 1) * 16;

    float ls[8], lsq[8];
    #pragma unroll
    for (int n = 0; n < 8; n++) { ls[n] = 0.f; lsq[n] = 0.f; }

    // ---- main loop: 68 pairs of m16 tiles, warp-strided -------------------
    for (int p = wid; p < 68; p += 8) {
        int q0 = p * 32;
        float c[2][4][4];
        #pragma unroll
        for (int mi = 0; mi < 2; mi++)
            #pragma unroll
            for (int j = 0; j < 4; j++)
                #pragma unroll
                for (int r = 0; r < 4; r++) c[mi][j][r] = 0.f;

        uint32_t ah = aHiBase + (uint32_t)q0 * 32;
        uint32_t al = aLoBase + (uint32_t)q0 * 32;

        #pragma unroll
        for (int ky = 0; ky < 5; ky++) {
            #pragma unroll
            for (int kx = 0; kx < 5; kx++) {
                int k = ky * 5 + kx;
                uint32_t off = (uint32_t)(ky * PW_ + kx) * 32;
                uint32_t ahi[2][4], alo[2][4], bh[2][4], bl[2][4];
                ldsm4(ahi[0], ah + off);
                ldsm4(ahi[1], ah + off + 512);
                ldsm4(alo[0], al + off);
                ldsm4(alo[1], al + off + 512);
                uint32_t wtap = wBase + (uint32_t)k * 1024;
                ldsm4(bh[0], wtap);
                ldsm4(bh[1], wtap + 512);
                ldsm4(bl[0], wtap + 25600);
                ldsm4(bl[1], wtap + 25600 + 512);
                #pragma unroll
                for (int mi = 0; mi < 2; mi++) {
                    #pragma unroll
                    for (int oh = 0; oh < 2; oh++) {
                        // pass 1: ahi*bhi ; pass 2: alo*bhi ; pass 3: ahi*blo
                        mma16816(c[mi][oh * 2 + 0], ahi[mi], bh[oh] + 0);
                        mma16816(c[mi][oh * 2 + 1], ahi[mi], bh[oh] + 2);
                        mma16816(c[mi][oh * 2 + 0], alo[mi], bh[oh] + 0);
                        mma16816(c[mi][oh * 2 + 1], alo[mi], bh[oh] + 2);
                        mma16816(c[mi][oh * 2 + 0], ahi[mi], bl[oh] + 0);
                        mma16816(c[mi][oh * 2 + 1], ahi[mi], bl[oh] + 2);
                    }
                }
            }
        }

        // ---- epilogue: bias+relu+proj, quad-reduce, store + stats ---------
        #pragma unroll
        for (int mi = 0; mi < 2; mi++) {
            #pragma unroll
            for (int half = 0; half < 2; half++) {
                int row = (lane >> 2) + half * 8;
                int q = q0 + mi * 16 + row;
                int y = q / PW_;
                int xe = q - y * PW_;
                bool valid = (xe >= 2 && xe < 66 && y < 32);
                int px = y * 64 + (xe - 2);
                float v[8];
                #pragma unroll
                for (int n = 0; n < 8; n++) v[n] = 0.f;
                if (valid && !sMask[px]) {
                    #pragma unroll
                    for (int j = 0; j < 4; j++) {
                        #pragma unroll
                        for (int e = 0; e < 2; e++) {
                            int oc = 8 * j + (lane & 3) * 2 + e;
                            float rv = fmaxf(c[mi][j][half * 2 + e] + sBias[oc],
                                             0.f);
                            const float* pt = sProjT + oc * 8;
                            #pragma unroll
                            for (int n = 0; n < 8; n++)
                                v[n] = fmaf(pt[n], rv, v[n]);
                        }
                    }
                }
                #pragma unroll
                for (int n = 0; n < 8; n++) {
                    v[n] += __shfl_xor_sync(0xffffffffu, v[n], 1);
                    v[n] += __shfl_xor_sync(0xffffffffu, v[n], 2);
                }
                if (valid) {
                    if ((lane & 3) == 0) {
                        #pragma unroll
                        for (int n = 0; n < 8; n++) {
                            ls[n] += v[n];
                            lsq[n] = fmaf(v[n], v[n], lsq[n]);
                        }
                    }
                    int n0 = (lane & 3) * 2;
                    size_t o0 = (((size_t)(b * 8 + n0) * T_ + t) << 11) + px;
                    out[o0] = v[n0];
                    out[o0 + ((size_t)T_ << 11)] = v[n0 + 1];
                }
            }
        }
    }

    // stats reduction
    #pragma unroll
    for (int k = 0; k < 16; k++) {
        float v = (k < 8) ? ls[k] : lsq[k - 8];
        #pragma unroll
        for (int off = 16; off; off >>= 1)
            v += __shfl_xor_sync(0xffffffffu, v, off);
        if (lane == 0) atomicAdd(&sRed[k], v);
    }
    __syncthreads();
    if (tid < 16) atomicAdd(&g_acc[tid], sRed[tid]);
}

// ---------------------------------------------------------------------------
// K3 stats
// ---------------------------------------------------------------------------
__global__ void stats_kernel(const float* __restrict__ gamma,
                             const float* __restrict__ beta) {
    int n = threadIdx.x;
    if (n < 8) {
        float cnt  = g_cnt;
        float mean = g_acc[n] / cnt;
        float var  = g_acc[8 + n] / cnt - mean * mean;
        var = fmaxf(var, 0.0f);
        float inv = rsqrtf(var + 1e-5f);
        float sc  = gamma[n] * inv;
        g_scale[n] = sc;
        g_shift[n] = beta[n] - mean * sc;
    }
}

// ---------------------------------------------------------------------------
// K4 BN apply
// ---------------------------------------------------------------------------
__global__ void bn_apply_kernel(float* __restrict__ out,
                                const int* __restrict__ mask) {
    int idx = blockIdx.x * 256 + threadIdx.x;
    int nlin = idx >> 16;
    int n = nlin & 7;
    int bb = nlin >> 3;
    int l4 = idx & 511;
    int4 m = *reinterpret_cast<const int4*>(mask + bb * L_ + l4 * 4);
    float4* p = reinterpret_cast<float4*>(out) + idx;
    float4 v = *p;
    float sc = g_scale[n], sh = g_shift[n];
    v.x = m.x ? v.x : fmaf(v.x, sc, sh);
    v.y = m.y ? v.y : fmaf(v.y, sc, sh);
    v.z = m.z ? v.z : fmaf(v.z, sc, sh);
    v.w = m.w ? v.w : fmaf(v.w, sc, sh);
    *p = v;
}

// ---------------------------------------------------------------------------
extern "C" void kernel_launch(void* const* d_in, const int* in_sizes, int n_in,
                              void* d_out, int out_size) {
    const float* prev  = (const float*)d_in[0];
    const float* curr  = (const float*)d_in[1];
    const int*   mask  = (const int*)d_in[2];
    const float* convw = (const float*)d_in[4];
    const float* convb = (const float*)d_in[5];
    const float* projw = (const float*)d_in[6];
    const float* gamma = (const float*)d_in[7];
    const float* beta  = (const float*)d_in[8];
    float* out = (float*)d_out;

    cudaFuncSetAttribute(conv_kernel,
                         cudaFuncAttributeMaxDynamicSharedMemorySize,
                         SMEM_TOTAL);

    prep_kernel<<<1, 256>>>(mask);
    wprep_kernel<<<25, 512>>>(convw);
    cumsum_kernel<<<256, 256>>>(prev, curr);
    conv_kernel<<<B_ * T_, 256, SMEM_TOTAL>>>(convb, projw, mask, out);
    stats_kernel<<<1, 32>>>(gamma, beta);
    bn_apply_kernel<<<(B_ * NH_ * T_ * L_ / 4) / 256, 256>>>(out, mask);
}

// round 7
// speedup vs baseline: 1.4931x; 1.0556x over previous
#include <cuda_runtime.h>
#include <cuda_bf16.h>
#include <cstdint>
#include <cstddef>

// ---------------------------------------------------------------------------
// AttentionRefinementModule — mma.sync bf16 implicit-GEMM pipeline (sm_100
// baseline target; tcgen05 unavailable in harness).
// R7: M-tile widened 32->64 ext-pixels per mainloop iteration to amortize
// B-fragment ldmatrix traffic (L1TEX was 81.5% = binding; tensor 42.7%).
// ---------------------------------------------------------------------------

#define B_    8
#define T_    128
#define NH_   8
#define CIN_  16
#define COUT_ 32
#define H_    32
#define W_    64
#define L_    2048
#define PW_   68            // padded width (x pad 2 each side)
#define PH_   36            // padded rows  (y pad 2 each side)

__device__ float g_cum[(size_t)B_ * T_ * CIN_ * L_];   // 128 MB scratch
__device__ __nv_bfloat16 g_wp[2 * 25 * COUT_ * CIN_];  // hi/lo weight planes
__device__ float g_acc[16];
__device__ float g_cnt;
__device__ float g_scale[8];
__device__ float g_shift[8];

// ---- smem layout (bytes) --------------------------------------------------
#define OFF_RED   16       // 16 floats
#define OFF_BIAS  80       // 32 floats
#define OFF_PROJ  256      // 256 floats, transposed [oc][n]
#define OFF_MASK  1280     // 2048 bytes
#define OFF_W     3328     // 51200 B: [plane][tap][oc][ic] bf16
#define OFF_AHI   54528    // 128 guard + 2448*32 + 128 tail = 78592 B
#define OFF_ALO   133120
#define SMEM_TOTAL 211712

// ---- PTX helpers ----------------------------------------------------------
__device__ __forceinline__ uint32_t smem_u32(const void* p) {
    uint32_t a;
    asm("{ .reg .u64 t; cvta.to.shared.u64 t, %1; cvt.u32.u64 %0, t; }"
        : "=r"(a) : "l"(p));
    return a;
}
__device__ __forceinline__ void ldsm4(uint32_t* r, uint32_t addr) {
    asm volatile("ldmatrix.sync.aligned.m8n8.x4.shared.b16 {%0,%1,%2,%3}, [%4];"
                 : "=r"(r[0]), "=r"(r[1]), "=r"(r[2]), "=r"(r[3]) : "r"(addr));
}
__device__ __forceinline__ void mma16816(float* c, const uint32_t* a,
                                         const uint32_t* b) {
    asm volatile(
        "mma.sync.aligned.m16n8k16.row.col.f32.bf16.bf16.f32 "
        "{%0,%1,%2,%3}, {%4,%5,%6,%7}, {%8,%9}, {%0,%1,%2,%3};"
        : "+f"(c[0]), "+f"(c[1]), "+f"(c[2]), "+f"(c[3])
        : "r"(a[0]), "r"(a[1]), "r"(a[2]), "r"(a[3]), "r"(b[0]), "r"(b[1]));
}

// ---------------------------------------------------------------------------
// K0 prep
// ---------------------------------------------------------------------------
__global__ void prep_kernel(const int* __restrict__ mask) {
    __shared__ int scnt;
    int tid = threadIdx.x;
    if (tid == 0) scnt = 0;
    if (tid < 16) g_acc[tid] = 0.0f;
    __syncthreads();
    int c = 0;
    for (int i = tid; i < B_ * L_; i += 256) c += (mask[i] == 0);
    #pragma unroll
    for (int off = 16; off; off >>= 1) c += __shfl_xor_sync(0xffffffffu, c, off);
    if ((tid & 31) == 0) atomicAdd(&scnt, c);
    __syncthreads();
    if (tid == 0) g_cnt = fmaxf(128.0f * (float)scnt, 1.0f);
}

// ---------------------------------------------------------------------------
// Kw: weight split hi/lo, layout [plane][tap][oc][ic]
// ---------------------------------------------------------------------------
__global__ void wprep_kernel(const float* __restrict__ convw) {
    int idx = blockIdx.x * 512 + threadIdx.x;
    if (idx >= 12800) return;
    int oc = idx / 400;
    int r  = idx - oc * 400;
    int ic = r / 25;
    int k  = r - ic * 25;            // tap = ky*5+kx
    float w = convw[idx];
    __nv_bfloat16 wh = __float2bfloat16_rn(w);
    __nv_bfloat16 wl = __float2bfloat16_rn(w - __bfloat162float(wh));
    g_wp[(k * 32 + oc) * 16 + ic] = wh;
    g_wp[12800 + (k * 32 + oc) * 16 + ic] = wl;
}

// ---------------------------------------------------------------------------
// K1 cumsum
// ---------------------------------------------------------------------------
__global__ void cumsum_kernel(const float* __restrict__ prev,
                              const float* __restrict__ curr) {
    int tid = blockIdx.x * blockDim.x + threadIdx.x;
    int b   = tid >> 13;
    int r   = tid & 8191;
    int ch  = r >> 9;
    int l4  = r & 511;
    const float* src0 = (ch < 8)
        ? prev + (size_t)(b * 8 + ch) * T_ * L_
        : curr + (size_t)(b * 8 + (ch - 8)) * T_ * L_;
    const float4* src = reinterpret_cast<const float4*>(src0) + l4;
    float4* dst = reinterpret_cast<float4*>(
        g_cum + ((size_t)(b * T_) * CIN_ + ch) * L_) + l4;
    float4 run = make_float4(0.f, 0.f, 0.f, 0.f);
    float4 nxt = src[0];
    for (int t = 0; t < T_; t++) {
        float4 cur = nxt;
        if (t < T_ - 1) nxt = src[(size_t)(t + 1) * (L_ / 4)];
        dst[(size_t)t * (CIN_ * L_ / 4)] = run;
        run.x += cur.x; run.y += cur.y; run.z += cur.z; run.w += cur.w;
    }
}

// ---------------------------------------------------------------------------
// K2 conv via mma.sync bf16 implicit GEMM, M=64 per mainloop iteration.
// Ext pixel grid: q in [0,2176), q = oy*68+ox+2 for valid outputs.
// A row for (q, ky, kx) lives at plane + 128 + (q + ky*68 + kx - 2)*32.
// ---------------------------------------------------------------------------
__global__ void __launch_bounds__(256)
conv_kernel(const float* __restrict__ convb,
            const float* __restrict__ projw,
            const int* __restrict__ mask,
            float* __restrict__ out) {
    extern __shared__ char sm[];
    uint32_t sb = smem_u32(sm);
    int tid = threadIdx.x;
    int wid = tid >> 5;
    int lane = tid & 31;
    int bt = blockIdx.x;
    int b  = bt >> 7;
    int t  = bt & 127;

    float* sRed   = reinterpret_cast<float*>(sm + OFF_RED);
    float* sBias  = reinterpret_cast<float*>(sm + OFF_BIAS);
    float* sProjT = reinterpret_cast<float*>(sm + OFF_PROJ);
    unsigned char* sMask = reinterpret_cast<unsigned char*>(sm + OFF_MASK);

    // ---- staging ----------------------------------------------------------
    int4 z4 = make_int4(0, 0, 0, 0);
    int4* planes = reinterpret_cast<int4*>(sm + OFF_AHI);
    for (int j = tid; j < (2 * 78592) / 16; j += 256) planes[j] = z4;
    {
        const int4* src = reinterpret_cast<const int4*>(g_wp);
        int4* dst = reinterpret_cast<int4*>(sm + OFF_W);
        for (int j = tid; j < 3200; j += 256) dst[j] = src[j];
    }
    if (tid < 16) sRed[tid] = 0.0f;
    if (tid < 32) sBias[tid] = convb[tid];
    { // transpose proj to [oc][n]
        int n = tid >> 5, oc = tid & 31;
        sProjT[oc * 8 + n] = projw[tid];
    }
    for (int j = tid; j < L_; j += 256)
        sMask[j] = (mask[b * L_ + j] != 0) ? 1 : 0;
    __syncthreads();

    // fp32 [ch][px] -> bf16 hi/lo channel-last padded image
    {
        const float* src = g_cum + (size_t)bt * CIN_ * L_;
        for (int it = 0; it < 8; it++) {
            int px = tid + it * 256;
            uint32_t h[8], l[8];
            #pragma unroll
            for (int cp = 0; cp < 8; cp++) {
                float v0 = src[(2 * cp) * L_ + px];
                float v1 = src[(2 * cp + 1) * L_ + px];
                __nv_bfloat16 h0 = __float2bfloat16_rn(v0);
                __nv_bfloat16 h1 = __float2bfloat16_rn(v1);
                __nv_bfloat16 l0 = __float2bfloat16_rn(v0 - __bfloat162float(h0));
                __nv_bfloat16 l1 = __float2bfloat16_rn(v1 - __bfloat162float(h1));
                h[cp] = ((uint32_t)*reinterpret_cast<uint16_t*>(&h1) << 16)
                      | (uint32_t)*reinterpret_cast<uint16_t*>(&h0);
                l[cp] = ((uint32_t)*reinterpret_cast<uint16_t*>(&l1) << 16)
                      | (uint32_t)*reinterpret_cast<uint16_t*>(&l0);
            }
            int y = px >> 6, x = px & 63;
            int byteoff = 128 + ((y + 2) * PW_ + x + 2) * 32;
            uint4* dh = reinterpret_cast<uint4*>(sm + OFF_AHI + byteoff);
            uint4* dl = reinterpret_cast<uint4*>(sm + OFF_ALO + byteoff);
            dh[0] = make_uint4(h[0], h[1], h[2], h[3]);
            dh[1] = make_uint4(h[4], h[5], h[6], h[7]);
            dl[0] = make_uint4(l[0], l[1], l[2], l[3]);
            dl[1] = make_uint4(l[4], l[5], l[6], l[7]);
        }
    }
    __syncthreads();

    // ---- per-thread ldmatrix base addresses -------------------------------
    uint32_t aHiBase = sb + OFF_AHI + 128 - 64
                     + (uint32_t)(lane & 15) * 32 + (uint32_t)(lane >> 4) * 16;
    uint32_t aLoBase = aHiBase + (OFF_ALO - OFF_AHI);
    // B (x4 non-trans of [oc][ic] rows): {b0,b1} oc-octet0, {b0,b1} oc-octet1
    uint32_t wBase = sb + OFF_W
                   + (uint32_t)((lane & 7) + ((lane >> 4) << 3)) * 32
                   + (uint32_t)((lane >> 3) & 1) * 16;

    float ls[8], lsq[8];
    #pragma unroll
    for (int n = 0; n < 8; n++) { ls[n] = 0.f; lsq[n] = 0.f; }

    // ---- main loop: 34 chunks of M=64 (4 m16 tiles), warp-strided ---------
    for (int p = wid; p < 34; p += 8) {
        int q0 = p * 64;
        float c[4][4][4];
        #pragma unroll
        for (int mi = 0; mi < 4; mi++)
            #pragma unroll
            for (int j = 0; j < 4; j++)
                #pragma unroll
                for (int r = 0; r < 4; r++) c[mi][j][r] = 0.f;

        uint32_t ah = aHiBase + (uint32_t)q0 * 32;
        uint32_t al = aLoBase + (uint32_t)q0 * 32;

        #pragma unroll
        for (int ky = 0; ky < 5; ky++) {
            #pragma unroll
            for (int kx = 0; kx < 5; kx++) {
                int k = ky * 5 + kx;
                uint32_t off = (uint32_t)(ky * PW_ + kx) * 32;
                uint32_t bh[2][4], bl[2][4];
                uint32_t wtap = wBase + (uint32_t)k * 1024;
                ldsm4(bh[0], wtap);
                ldsm4(bh[1], wtap + 512);
                ldsm4(bl[0], wtap + 25600);
                ldsm4(bl[1], wtap + 25600 + 512);
                #pragma unroll
                for (int mi = 0; mi < 4; mi++) {
                    uint32_t ahi[4], alo[4];
                    ldsm4(ahi, ah + off + (uint32_t)mi * 512);
                    ldsm4(alo, al + off + (uint32_t)mi * 512);
                    #pragma unroll
                    for (int oh = 0; oh < 2; oh++) {
                        // pass 1: ahi*bhi ; pass 2: alo*bhi ; pass 3: ahi*blo
                        mma16816(c[mi][oh * 2 + 0], ahi, bh[oh] + 0);
                        mma16816(c[mi][oh * 2 + 1], ahi, bh[oh] + 2);
                        mma16816(c[mi][oh * 2 + 0], alo, bh[oh] + 0);
                        mma16816(c[mi][oh * 2 + 1], alo, bh[oh] + 2);
                        mma16816(c[mi][oh * 2 + 0], ahi, bl[oh] + 0);
                        mma16816(c[mi][oh * 2 + 1], ahi, bl[oh] + 2);
                    }
                }
            }
        }

        // ---- epilogue: bias+relu+proj, quad-reduce, store + stats ---------
        #pragma unroll
        for (int mi = 0; mi < 4; mi++) {
            #pragma unroll
            for (int half = 0; half < 2; half++) {
                int row = (lane >> 2) + half * 8;
                int q = q0 + mi * 16 + row;
                int y = q / PW_;
                int xe = q - y * PW_;
                bool valid = (xe >= 2 && xe < 66 && y < 32);
                int px = y * 64 + (xe - 2);
                float v[8];
                #pragma unroll
                for (int n = 0; n < 8; n++) v[n] = 0.f;
                if (valid && !sMask[px]) {
                    #pragma unroll
                    for (int j = 0; j < 4; j++) {
                        #pragma unroll
                        for (int e = 0; e < 2; e++) {
                            int oc = 8 * j + (lane & 3) * 2 + e;
                            float rv = fmaxf(c[mi][j][half * 2 + e] + sBias[oc],
                                             0.f);
                            const float* pt = sProjT + oc * 8;
                            #pragma unroll
                            for (int n = 0; n < 8; n++)
                                v[n] = fmaf(pt[n], rv, v[n]);
                        }
                    }
                }
                #pragma unroll
                for (int n = 0; n < 8; n++) {
                    v[n] += __shfl_xor_sync(0xffffffffu, v[n], 1);
                    v[n] += __shfl_xor_sync(0xffffffffu, v[n], 2);
                }
                if (valid) {
                    if ((lane & 3) == 0) {
                        #pragma unroll
                        for (int n = 0; n < 8; n++) {
                            ls[n] += v[n];
                            lsq[n] = fmaf(v[n], v[n], lsq[n]);
                        }
                    }
                    int n0 = (lane & 3) * 2;
                    size_t o0 = (((size_t)(b * 8 + n0) * T_ + t) << 11) + px;
                    out[o0] = v[n0];
                    out[o0 + ((size_t)T_ << 11)] = v[n0 + 1];
                }
            }
        }
    }

    // stats reduction
    #pragma unroll
    for (int k = 0; k < 16; k++) {
        float v = (k < 8) ? ls[k] : lsq[k - 8];
        #pragma unroll
        for (int off = 16; off; off >>= 1)
            v += __shfl_xor_sync(0xffffffffu, v, off);
        if (lane == 0) atomicAdd(&sRed[k], v);
    }
    __syncthreads();
    if (tid < 16) atomicAdd(&g_acc[tid], sRed[tid]);
}

// ---------------------------------------------------------------------------
// K3 stats
// ---------------------------------------------------------------------------
__global__ void stats_kernel(const float* __restrict__ gamma,
                             const float* __restrict__ beta) {
    int n = threadIdx.x;
    if (n < 8) {
        float cnt  = g_cnt;
        float mean = g_acc[n] / cnt;
        float var  = g_acc[8 + n] / cnt - mean * mean;
        var = fmaxf(var, 0.0f);
        float inv = rsqrtf(var + 1e-5f);
        float sc  = gamma[n] * inv;
        g_scale[n] = sc;
        g_shift[n] = beta[n] - mean * sc;
    }
}

// ---------------------------------------------------------------------------
// K4 BN apply
// ---------------------------------------------------------------------------
__global__ void bn_apply_kernel(float* __restrict__ out,
                                const int* __restrict__ mask) {
    int idx = blockIdx.x * 256 + threadIdx.x;
    int nlin = idx >> 16;
    int n = nlin & 7;
    int bb = nlin >> 3;
    int l4 = idx & 511;
    int4 m = *reinterpret_cast<const int4*>(mask + bb * L_ + l4 * 4);
    float4* p = reinterpret_cast<float4*>(out) + idx;
    float4 v = *p;
    float sc = g_scale[n], sh = g_shift[n];
    v.x = m.x ? v.x : fmaf(v.x, sc, sh);
    v.y = m.y ? v.y : fmaf(v.y, sc, sh);
    v.z = m.z ? v.z : fmaf(v.z, sc, sh);
    v.w = m.w ? v.w : fmaf(v.w, sc, sh);
    *p = v;
}

// ---------------------------------------------------------------------------
extern "C" void kernel_launch(void* const* d_in, const int* in_sizes, int n_in,
                              void* d_out, int out_size) {
    const float* prev  = (const float*)d_in[0];
    const float* curr  = (const float*)d_in[1];
    const int*   mask  = (const int*)d_in[2];
    const float* convw = (const float*)d_in[4];
    const float* convb = (const float*)d_in[5];
    const float* projw = (const float*)d_in[6];
    const float* gamma = (const float*)d_in[7];
    const float* beta  = (const float*)d_in[8];
    float* out = (float*)d_out;

    cudaFuncSetAttribute(conv_kernel,
                         cudaFuncAttributeMaxDynamicSharedMemorySize,
                         SMEM_TOTAL);

    prep_kernel<<<1, 256>>>(mask);
    wprep_kernel<<<25, 512>>>(convw);
    cumsum_kernel<<<256, 256>>>(prev, curr);
    conv_kernel<<<B_ * T_, 256, SMEM_TOTAL>>>(convb, projw, mask, out);
    stats_kernel<<<1, 32>>>(gamma, beta);
    bn_apply_kernel<<<(B_ * NH_ * T_ * L_ / 4) / 256, 256>>>(out, mask);
}

// round 8
// speedup vs baseline: 1.6861x; 1.1292x over previous
#include <cuda_runtime.h>
#include <cuda_bf16.h>
#include <cstdint>
#include <cstddef>

// ---------------------------------------------------------------------------
// AttentionRefinementModule — mma.sync bf16 implicit-GEMM pipeline (sm_100
// baseline target; tcgen05 unavailable in harness).
// R8: 512-thread CTAs (16 warps/SM, occupancy was the limiter at 12.5%),
// M-tile 48 for 96% warp balance, BN stats moved to a separate reduction.
// ---------------------------------------------------------------------------

#define B_    8
#define T_    128
#define NH_   8
#define CIN_  16
#define COUT_ 32
#define H_    32
#define W_    64
#define L_    2048
#define PW_   68            // padded width (x pad 2 each side)

__device__ float g_cum[(size_t)B_ * T_ * CIN_ * L_];   // 128 MB scratch
__device__ __nv_bfloat16 g_wp[2 * 25 * COUT_ * CIN_];  // hi/lo weight planes
__device__ float g_acc[16];
__device__ float g_cnt;
__device__ float g_scale[8];
__device__ float g_shift[8];

// ---- smem layout (bytes) --------------------------------------------------
#define OFF_BIAS  80       // 32 floats
#define OFF_PROJ  256      // 256 floats, transposed [oc][n]
#define OFF_MASK  1280     // 2048 bytes
#define OFF_W     3328     // 51200 B: [plane][tap][oc][ic] bf16
#define OFF_AHI   54528
#define APLANE    79616    // 64 front guard + rows up to 2483 + tail
#define OFF_ALO   (OFF_AHI + APLANE)
#define SMEM_TOTAL (OFF_AHI + 2 * APLANE)   // 213760 <= 227KB

// ---- PTX helpers ----------------------------------------------------------
__device__ __forceinline__ uint32_t smem_u32(const void* p) {
    uint32_t a;
    asm("{ .reg .u64 t; cvta.to.shared.u64 t, %1; cvt.u32.u64 %0, t; }"
        : "=r"(a) : "l"(p));
    return a;
}
__device__ __forceinline__ void ldsm4(uint32_t* r, uint32_t addr) {
    asm volatile("ldmatrix.sync.aligned.m8n8.x4.shared.b16 {%0,%1,%2,%3}, [%4];"
                 : "=r"(r[0]), "=r"(r[1]), "=r"(r[2]), "=r"(r[3]) : "r"(addr));
}
__device__ __forceinline__ void mma16816(float* c, const uint32_t* a,
                                         const uint32_t* b) {
    asm volatile(
        "mma.sync.aligned.m16n8k16.row.col.f32.bf16.bf16.f32 "
        "{%0,%1,%2,%3}, {%4,%5,%6,%7}, {%8,%9}, {%0,%1,%2,%3};"
        : "+f"(c[0]), "+f"(c[1]), "+f"(c[2]), "+f"(c[3])
        : "r"(a[0]), "r"(a[1]), "r"(a[2]), "r"(a[3]), "r"(b[0]), "r"(b[1]));
}

// ---------------------------------------------------------------------------
// K0 prep: zero accumulators + unmasked count
// ---------------------------------------------------------------------------
__global__ void prep_kernel(const int* __restrict__ mask) {
    __shared__ int scnt;
    int tid = threadIdx.x;
    if (tid == 0) scnt = 0;
    if (tid < 16) g_acc[tid] = 0.0f;
    __syncthreads();
    int c = 0;
    for (int i = tid; i < B_ * L_; i += 256) c += (mask[i] == 0);
    #pragma unroll
    for (int off = 16; off; off >>= 1) c += __shfl_xor_sync(0xffffffffu, c, off);
    if ((tid & 31) == 0) atomicAdd(&scnt, c);
    __syncthreads();
    if (tid == 0) g_cnt = fmaxf(128.0f * (float)scnt, 1.0f);
}

// ---------------------------------------------------------------------------
// Kw: weight split hi/lo, layout [plane][tap][oc][ic]
// ---------------------------------------------------------------------------
__global__ void wprep_kernel(const float* __restrict__ convw) {
    int idx = blockIdx.x * 512 + threadIdx.x;
    if (idx >= 12800) return;
    int oc = idx / 400;
    int r  = idx - oc * 400;
    int ic = r / 25;
    int k  = r - ic * 25;            // tap = ky*5+kx
    float w = convw[idx];
    __nv_bfloat16 wh = __float2bfloat16_rn(w);
    __nv_bfloat16 wl = __float2bfloat16_rn(w - __bfloat162float(wh));
    g_wp[(k * 32 + oc) * 16 + ic] = wh;
    g_wp[12800 + (k * 32 + oc) * 16 + ic] = wl;
}

// ---------------------------------------------------------------------------
// K1 cumsum
// ---------------------------------------------------------------------------
__global__ void cumsum_kernel(const float* __restrict__ prev,
                              const float* __restrict__ curr) {
    int tid = blockIdx.x * blockDim.x + threadIdx.x;
    int b   = tid >> 13;
    int r   = tid & 8191;
    int ch  = r >> 9;
    int l4  = r & 511;
    const float* src0 = (ch < 8)
        ? prev + (size_t)(b * 8 + ch) * T_ * L_
        : curr + (size_t)(b * 8 + (ch - 8)) * T_ * L_;
    const float4* src = reinterpret_cast<const float4*>(src0) + l4;
    float4* dst = reinterpret_cast<float4*>(
        g_cum + ((size_t)(b * T_) * CIN_ + ch) * L_) + l4;
    float4 run = make_float4(0.f, 0.f, 0.f, 0.f);
    float4 nxt = src[0];
    for (int t = 0; t < T_; t++) {
        float4 cur = nxt;
        if (t < T_ - 1) nxt = src[(size_t)(t + 1) * (L_ / 4)];
        dst[(size_t)t * (CIN_ * L_ / 4)] = run;
        run.x += cur.x; run.y += cur.y; run.z += cur.z; run.w += cur.w;
    }
}

// ---------------------------------------------------------------------------
// K2 conv via mma.sync bf16 implicit GEMM. 512 threads, M=48 per chunk.
// Ext pixel grid: q in [0,2208), q = oy*68+ox+2 valid for oy<32, 2<=xe<66.
// A row for (q, ky, kx) at plane + 64 + (q + ky*68 + kx)*32   (pixel q-2).
// ---------------------------------------------------------------------------
__global__ void __launch_bounds__(512)
conv_kernel(const float* __restrict__ convb,
            const float* __restrict__ projw,
            const int* __restrict__ mask,
            float* __restrict__ out) {
    extern __shared__ char sm[];
    uint32_t sb = smem_u32(sm);
    int tid = threadIdx.x;
    int wid = tid >> 5;
    int lane = tid & 31;
    int bt = blockIdx.x;
    int b  = bt >> 7;
    int t  = bt & 127;

    float* sBias  = reinterpret_cast<float*>(sm + OFF_BIAS);
    float* sProjT = reinterpret_cast<float*>(sm + OFF_PROJ);
    unsigned char* sMask = reinterpret_cast<unsigned char*>(sm + OFF_MASK);

    // ---- staging ----------------------------------------------------------
    int4 z4 = make_int4(0, 0, 0, 0);
    int4* planes = reinterpret_cast<int4*>(sm + OFF_AHI);
    for (int j = tid; j < (2 * APLANE) / 16; j += 512) planes[j] = z4;
    {
        const int4* src = reinterpret_cast<const int4*>(g_wp);
        int4* dst = reinterpret_cast<int4*>(sm + OFF_W);
        for (int j = tid; j < 3200; j += 512) dst[j] = src[j];
    }
    if (tid < 32) sBias[tid] = convb[tid];
    if (tid < 256) { // transpose proj to [oc][n]
        int n = tid >> 5, oc = tid & 31;
        sProjT[oc * 8 + n] = projw[tid];
    }
    for (int j = tid; j < L_; j += 512)
        sMask[j] = (mask[b * L_ + j] != 0) ? 1 : 0;
    __syncthreads();

    // fp32 [ch][px] -> bf16 hi/lo channel-last padded image
    {
        const float* src = g_cum + (size_t)bt * CIN_ * L_;
        for (int px = tid; px < L_; px += 512) {
            uint32_t h[8], l[8];
            #pragma unroll
            for (int cp = 0; cp < 8; cp++) {
                float v0 = src[(2 * cp) * L_ + px];
                float v1 = src[(2 * cp + 1) * L_ + px];
                __nv_bfloat16 h0 = __float2bfloat16_rn(v0);
                __nv_bfloat16 h1 = __float2bfloat16_rn(v1);
                __nv_bfloat16 l0 = __float2bfloat16_rn(v0 - __bfloat162float(h0));
                __nv_bfloat16 l1 = __float2bfloat16_rn(v1 - __bfloat162float(h1));
                h[cp] = ((uint32_t)*reinterpret_cast<uint16_t*>(&h1) << 16)
                      | (uint32_t)*reinterpret_cast<uint16_t*>(&h0);
                l[cp] = ((uint32_t)*reinterpret_cast<uint16_t*>(&l1) << 16)
                      | (uint32_t)*reinterpret_cast<uint16_t*>(&l0);
            }
            int y = px >> 6, x = px & 63;
            int byteoff = 128 + ((y + 2) * PW_ + x + 2) * 32;
            uint4* dh = reinterpret_cast<uint4*>(sm + OFF_AHI + byteoff);
            uint4* dl = reinterpret_cast<uint4*>(sm + OFF_ALO + byteoff);
            dh[0] = make_uint4(h[0], h[1], h[2], h[3]);
            dh[1] = make_uint4(h[4], h[5], h[6], h[7]);
            dl[0] = make_uint4(l[0], l[1], l[2], l[3]);
            dl[1] = make_uint4(l[4], l[5], l[6], l[7]);
        }
    }
    __syncthreads();

    // ---- per-thread ldmatrix base addresses -------------------------------
    uint32_t aHiBase = sb + OFF_AHI + 64
                     + (uint32_t)(lane & 15) * 32 + (uint32_t)(lane >> 4) * 16;
    uint32_t aLoBase = aHiBase + APLANE;
    // B (x4 non-trans of [oc][ic] rows): {b0,b1} oc-octet0, {b0,b1} oc-octet1
    uint32_t wBase = sb + OFF_W
                   + (uint32_t)((lane & 7) + ((lane >> 4) << 3)) * 32
                   + (uint32_t)((lane >> 3) & 1) * 16;

    // ---- main loop: 46 chunks of M=48 (3 m16 tiles), warp-strided ---------
    for (int p = wid; p < 46; p += 16) {
        int q0 = p * 48;
        float c[3][4][4];
        #pragma unroll
        for (int mi = 0; mi < 3; mi++)
            #pragma unroll
            for (int j = 0; j < 4; j++)
                #pragma unroll
                for (int r = 0; r < 4; r++) c[mi][j][r] = 0.f;

        uint32_t ah = aHiBase + (uint32_t)q0 * 32;
        uint32_t al = aLoBase + (uint32_t)q0 * 32;

        #pragma unroll
        for (int ky = 0; ky < 5; ky++) {
            #pragma unroll
            for (int kx = 0; kx < 5; kx++) {
                int k = ky * 5 + kx;
                uint32_t off = (uint32_t)(ky * PW_ + kx) * 32;
                uint32_t bh[2][4], bl[2][4];
                uint32_t wtap = wBase + (uint32_t)k * 1024;
                ldsm4(bh[0], wtap);
                ldsm4(bh[1], wtap + 512);
                ldsm4(bl[0], wtap + 25600);
                ldsm4(bl[1], wtap + 25600 + 512);
                #pragma unroll
                for (int mi = 0; mi < 3; mi++) {
                    uint32_t ahi[4], alo[4];
                    ldsm4(ahi, ah + off + (uint32_t)mi * 512);
                    ldsm4(alo, al + off + (uint32_t)mi * 512);
                    #pragma unroll
                    for (int oh = 0; oh < 2; oh++) {
                        // pass 1: ahi*bhi ; pass 2: alo*bhi ; pass 3: ahi*blo
                        mma16816(c[mi][oh * 2 + 0], ahi, bh[oh] + 0);
                        mma16816(c[mi][oh * 2 + 1], ahi, bh[oh] + 2);
                        mma16816(c[mi][oh * 2 + 0], alo, bh[oh] + 0);
                        mma16816(c[mi][oh * 2 + 1], alo, bh[oh] + 2);
                        mma16816(c[mi][oh * 2 + 0], ahi, bl[oh] + 0);
                        mma16816(c[mi][oh * 2 + 1], ahi, bl[oh] + 2);
                    }
                }
            }
        }

        // ---- epilogue: bias+relu+proj, quad-reduce, store -----------------
        #pragma unroll
        for (int mi = 0; mi < 3; mi++) {
            #pragma unroll
            for (int half = 0; half < 2; half++) {
                int row = (lane >> 2) + half * 8;
                int q = q0 + mi * 16 + row;
                int y = q / PW_;
                int xe = q - y * PW_;
                bool valid = (xe >= 2 && xe < 66 && y < 32);
                int px = y * 64 + (xe - 2);
                float v[8];
                #pragma unroll
                for (int n = 0; n < 8; n++) v[n] = 0.f;
                if (valid && !sMask[px]) {
                    #pragma unroll
                    for (int j = 0; j < 4; j++) {
                        #pragma unroll
                        for (int e = 0; e < 2; e++) {
                            int oc = 8 * j + (lane & 3) * 2 + e;
                            float rv = fmaxf(c[mi][j][half * 2 + e] + sBias[oc],
                                             0.f);
                            const float* pt = sProjT + oc * 8;
                            #pragma unroll
                            for (int n = 0; n < 8; n++)
                                v[n] = fmaf(pt[n], rv, v[n]);
                        }
                    }
                }
                #pragma unroll
                for (int n = 0; n < 8; n++) {
                    v[n] += __shfl_xor_sync(0xffffffffu, v[n], 1);
                    v[n] += __shfl_xor_sync(0xffffffffu, v[n], 2);
                }
                if (valid) {
                    int n0 = (lane & 3) * 2;
                    size_t o0 = (((size_t)(b * 8 + n0) * T_ + t) << 11) + px;
                    out[o0] = v[n0];
                    out[o0 + ((size_t)T_ << 11)] = v[n0 + 1];
                }
            }
        }
    }
}

// ---------------------------------------------------------------------------
// K2b: per-channel sum/sumsq over stored pre-BN output (masked entries are 0)
// grid 1024 x 256 threads: block bk handles 16384 contiguous floats, all one n
// ---------------------------------------------------------------------------
__global__ void sum_kernel(const float* __restrict__ out) {
    __shared__ float sred[2];
    int tid = threadIdx.x;
    int bk  = blockIdx.x;
    int n   = (bk >> 4) & 7;
    if (tid == 0) { sred[0] = 0.f; sred[1] = 0.f; }
    __syncthreads();
    const float4* p = reinterpret_cast<const float4*>(out) + (size_t)bk * 4096;
    float s = 0.f, sq = 0.f;
    for (int i = tid; i < 4096; i += 256) {
        float4 v = p[i];
        s  += v.x + v.y + v.z + v.w;
        sq += v.x * v.x + v.y * v.y + v.z * v.z + v.w * v.w;
    }
    #pragma unroll
    for (int off = 16; off; off >>= 1) {
        s  += __shfl_xor_sync(0xffffffffu, s, off);
        sq += __shfl_xor_sync(0xffffffffu, sq, off);
    }
    if ((tid & 31) == 0) {
        atomicAdd(&sred[0], s);
        atomicAdd(&sred[1], sq);
    }
    __syncthreads();
    if (tid == 0) {
        atomicAdd(&g_acc[n], sred[0]);
        atomicAdd(&g_acc[8 + n], sred[1]);
    }
}

// ---------------------------------------------------------------------------
// K3 stats
// ---------------------------------------------------------------------------
__global__ void stats_kernel(const float* __restrict__ gamma,
                             const float* __restrict__ beta) {
    int n = threadIdx.x;
    if (n < 8) {
        float cnt  = g_cnt;
        float mean = g_acc[n] / cnt;
        float var  = g_acc[8 + n] / cnt - mean * mean;
        var = fmaxf(var, 0.0f);
        float inv = rsqrtf(var + 1e-5f);
        float sc  = gamma[n] * inv;
        g_scale[n] = sc;
        g_shift[n] = beta[n] - mean * sc;
    }
}

// ---------------------------------------------------------------------------
// K4 BN apply
// ---------------------------------------------------------------------------
__global__ void bn_apply_kernel(float* __restrict__ out,
                                const int* __restrict__ mask) {
    int idx = blockIdx.x * 256 + threadIdx.x;
    int nlin = idx >> 16;
    int n = nlin & 7;
    int bb = nlin >> 3;
    int l4 = idx & 511;
    int4 m = *reinterpret_cast<const int4*>(mask + bb * L_ + l4 * 4);
    float4* p = reinterpret_cast<float4*>(out) + idx;
    float4 v = *p;
    float sc = g_scale[n], sh = g_shift[n];
    v.x = m.x ? v.x : fmaf(v.x, sc, sh);
    v.y = m.y ? v.y : fmaf(v.y, sc, sh);
    v.z = m.z ? v.z : fmaf(v.z, sc, sh);
    v.w = m.w ? v.w : fmaf(v.w, sc, sh);
    *p = v;
}

// ---------------------------------------------------------------------------
extern "C" void kernel_launch(void* const* d_in, const int* in_sizes, int n_in,
                              void* d_out, int out_size) {
    const float* prev  = (const float*)d_in[0];
    const float* curr  = (const float*)d_in[1];
    const int*   mask  = (const int*)d_in[2];
    const float* convw = (const float*)d_in[4];
    const float* convb = (const float*)d_in[5];
    const float* projw = (const float*)d_in[6];
    const float* gamma = (const float*)d_in[7];
    const float* beta  = (const float*)d_in[8];
    float* out = (float*)d_out;

    cudaFuncSetAttribute(conv_kernel,
                         cudaFuncAttributeMaxDynamicSharedMemorySize,
                         SMEM_TOTAL);

    prep_kernel<<<1, 256>>>(mask);
    wprep_kernel<<<25, 512>>>(convw);
    cumsum_kernel<<<256, 256>>>(prev, curr);
    conv_kernel<<<B_ * T_, 512, SMEM_TOTAL>>>(convb, projw, mask, out);
    sum_kernel<<<1024, 256>>>(out);
    stats_kernel<<<1, 32>>>(gamma, beta);
    bn_apply_kernel<<<(B_ * NH_ * T_ * L_ / 4) / 256, 256>>>(out, mask);
}

// round 10
// speedup vs baseline: 1.7486x; 1.0370x over previous
#include <cuda_runtime.h>
#include <cuda_bf16.h>
#include <cstdint>
#include <cstddef>

// ---------------------------------------------------------------------------
// AttentionRefinementModule — mma.sync bf16 implicit-GEMM pipeline (sm_100
// baseline target; tcgen05 unavailable in harness).
// R10 (= R9 resubmit): M-tile 48->96, 384-thread CTAs. L1/LDSM wavefronts
// are the wall (89.5%); wider M amortizes B loads: 1.11 -> 0.89 wf/mma.
// Outer chunk loop pinned no-unroll to bound live accumulator pressure.
// ---------------------------------------------------------------------------

#define B_    8
#define T_    128
#define NH_   8
#define CIN_  16
#define COUT_ 32
#define H_    32
#define W_    64
#define L_    2048
#define PW_   68            // padded width (x pad 2 each side)

__device__ float g_cum[(size_t)B_ * T_ * CIN_ * L_];   // 128 MB scratch
__device__ __nv_bfloat16 g_wp[2 * 25 * COUT_ * CIN_];  // hi/lo weight planes
__device__ float g_acc[16];
__device__ float g_cnt;
__device__ float g_scale[8];
__device__ float g_shift[8];

// ---- smem layout (bytes) --------------------------------------------------
#define OFF_BIAS  80       // 32 floats
#define OFF_PROJ  256      // 256 floats, transposed [oc][n]
#define OFF_MASK  1280     // 2048 bytes
#define OFF_W     3328     // 51200 B: [plane][tap][oc][ic] bf16
#define OFF_AHI   54528
#define APLANE    79616    // 64 front guard + rows up to 2483 + tail
#define OFF_ALO   (OFF_AHI + APLANE)
#define SMEM_TOTAL (OFF_AHI + 2 * APLANE)   // 213760

// ---- PTX helpers ----------------------------------------------------------
__device__ __forceinline__ uint32_t smem_u32(const void* p) {
    uint32_t a;
    asm("{ .reg .u64 t; cvta.to.shared.u64 t, %1; cvt.u32.u64 %0, t; }"
        : "=r"(a) : "l"(p));
    return a;
}
__device__ __forceinline__ void ldsm4(uint32_t* r, uint32_t addr) {
    asm volatile("ldmatrix.sync.aligned.m8n8.x4.shared.b16 {%0,%1,%2,%3}, [%4];"
                 : "=r"(r[0]), "=r"(r[1]), "=r"(r[2]), "=r"(r[3]) : "r"(addr));
}
__device__ __forceinline__ void mma16816(float* c, const uint32_t* a,
                                         const uint32_t* b) {
    asm volatile(
        "mma.sync.aligned.m16n8k16.row.col.f32.bf16.bf16.f32 "
        "{%0,%1,%2,%3}, {%4,%5,%6,%7}, {%8,%9}, {%0,%1,%2,%3};"
        : "+f"(c[0]), "+f"(c[1]), "+f"(c[2]), "+f"(c[3])
        : "r"(a[0]), "r"(a[1]), "r"(a[2]), "r"(a[3]), "r"(b[0]), "r"(b[1]));
}

// ---------------------------------------------------------------------------
// K0 prep: zero accumulators + unmasked count
// ---------------------------------------------------------------------------
__global__ void prep_kernel(const int* __restrict__ mask) {
    __shared__ int scnt;
    int tid = threadIdx.x;
    if (tid == 0) scnt = 0;
    if (tid < 16) g_acc[tid] = 0.0f;
    __syncthreads();
    int c = 0;
    for (int i = tid; i < B_ * L_; i += 256) c += (mask[i] == 0);
    #pragma unroll
    for (int off = 16; off; off >>= 1) c += __shfl_xor_sync(0xffffffffu, c, off);
    if ((tid & 31) == 0) atomicAdd(&scnt, c);
    __syncthreads();
    if (tid == 0) g_cnt = fmaxf(128.0f * (float)scnt, 1.0f);
}

// ---------------------------------------------------------------------------
// Kw: weight split hi/lo, layout [plane][tap][oc][ic]
// ---------------------------------------------------------------------------
__global__ void wprep_kernel(const float* __restrict__ convw) {
    int idx = blockIdx.x * 512 + threadIdx.x;
    if (idx >= 12800) return;
    int oc = idx / 400;
    int r  = idx - oc * 400;
    int ic = r / 25;
    int k  = r - ic * 25;            // tap = ky*5+kx
    float w = convw[idx];
    __nv_bfloat16 wh = __float2bfloat16_rn(w);
    __nv_bfloat16 wl = __float2bfloat16_rn(w - __bfloat162float(wh));
    g_wp[(k * 32 + oc) * 16 + ic] = wh;
    g_wp[12800 + (k * 32 + oc) * 16 + ic] = wl;
}

// ---------------------------------------------------------------------------
// K1 cumsum
// ---------------------------------------------------------------------------
__global__ void cumsum_kernel(const float* __restrict__ prev,
                              const float* __restrict__ curr) {
    int tid = blockIdx.x * blockDim.x + threadIdx.x;
    int b   = tid >> 13;
    int r   = tid & 8191;
    int ch  = r >> 9;
    int l4  = r & 511;
    const float* src0 = (ch < 8)
        ? prev + (size_t)(b * 8 + ch) * T_ * L_
        : curr + (size_t)(b * 8 + (ch - 8)) * T_ * L_;
    const float4* src = reinterpret_cast<const float4*>(src0) + l4;
    float4* dst = reinterpret_cast<float4*>(
        g_cum + ((size_t)(b * T_) * CIN_ + ch) * L_) + l4;
    float4 run = make_float4(0.f, 0.f, 0.f, 0.f);
    float4 nxt = src[0];
    for (int t = 0; t < T_; t++) {
        float4 cur = nxt;
        if (t < T_ - 1) nxt = src[(size_t)(t + 1) * (L_ / 4)];
        dst[(size_t)t * (CIN_ * L_ / 4)] = run;
        run.x += cur.x; run.y += cur.y; run.z += cur.z; run.w += cur.w;
    }
}

// ---------------------------------------------------------------------------
// K2 conv via mma.sync bf16 implicit GEMM. 384 threads, M=96 per chunk.
// Ext pixel grid: q in [0,2208), q = oy*68+ox+2 valid for oy<32, 2<=xe<66.
// A row for (q, ky, kx) at plane + 64 + (q + ky*68 + kx)*32   (pixel q-2).
// ---------------------------------------------------------------------------
__global__ void __launch_bounds__(384)
conv_kernel(const float* __restrict__ convb,
            const float* __restrict__ projw,
            const int* __restrict__ mask,
            float* __restrict__ out) {
    extern __shared__ char sm[];
    uint32_t sb = smem_u32(sm);
    int tid = threadIdx.x;
    int wid = tid >> 5;
    int lane = tid & 31;
    int bt = blockIdx.x;
    int b  = bt >> 7;
    int t  = bt & 127;

    float* sBias  = reinterpret_cast<float*>(sm + OFF_BIAS);
    float* sProjT = reinterpret_cast<float*>(sm + OFF_PROJ);
    unsigned char* sMask = reinterpret_cast<unsigned char*>(sm + OFF_MASK);

    // ---- staging ----------------------------------------------------------
    int4 z4 = make_int4(0, 0, 0, 0);
    int4* planes = reinterpret_cast<int4*>(sm + OFF_AHI);
    for (int j = tid; j < (2 * APLANE) / 16; j += 384) planes[j] = z4;
    {
        const int4* src = reinterpret_cast<const int4*>(g_wp);
        int4* dst = reinterpret_cast<int4*>(sm + OFF_W);
        for (int j = tid; j < 3200; j += 384) dst[j] = src[j];
    }
    if (tid < 32) sBias[tid] = convb[tid];
    if (tid < 256) { // transpose proj to [oc][n]
        int n = tid >> 5, oc = tid & 31;
        sProjT[oc * 8 + n] = projw[tid];
    }
    for (int j = tid; j < L_; j += 384)
        sMask[j] = (mask[b * L_ + j] != 0) ? 1 : 0;
    __syncthreads();

    // fp32 [ch][px] -> bf16 hi/lo channel-last padded image
    {
        const float* src = g_cum + (size_t)bt * CIN_ * L_;
        for (int px = tid; px < L_; px += 384) {
            uint32_t h[8], l[8];
            #pragma unroll
            for (int cp = 0; cp < 8; cp++) {
                float v0 = src[(2 * cp) * L_ + px];
                float v1 = src[(2 * cp + 1) * L_ + px];
                __nv_bfloat16 h0 = __float2bfloat16_rn(v0);
                __nv_bfloat16 h1 = __float2bfloat16_rn(v1);
                __nv_bfloat16 l0 = __float2bfloat16_rn(v0 - __bfloat162float(h0));
                __nv_bfloat16 l1 = __float2bfloat16_rn(v1 - __bfloat162float(h1));
                h[cp] = ((uint32_t)*reinterpret_cast<uint16_t*>(&h1) << 16)
                      | (uint32_t)*reinterpret_cast<uint16_t*>(&h0);
                l[cp] = ((uint32_t)*reinterpret_cast<uint16_t*>(&l1) << 16)
                      | (uint32_t)*reinterpret_cast<uint16_t*>(&l0);
            }
            int y = px >> 6, x = px & 63;
            int byteoff = 128 + ((y + 2) * PW_ + x + 2) * 32;
            uint4* dh = reinterpret_cast<uint4*>(sm + OFF_AHI + byteoff);
            uint4* dl = reinterpret_cast<uint4*>(sm + OFF_ALO + byteoff);
            dh[0] = make_uint4(h[0], h[1], h[2], h[3]);
            dh[1] = make_uint4(h[4], h[5], h[6], h[7]);
            dl[0] = make_uint4(l[0], l[1], l[2], l[3]);
            dl[1] = make_uint4(l[4], l[5], l[6], l[7]);
        }
    }
    __syncthreads();

    // ---- per-thread ldmatrix base addresses -------------------------------
    uint32_t aHiBase = sb + OFF_AHI + 64
                     + (uint32_t)(lane & 15) * 32 + (uint32_t)(lane >> 4) * 16;
    uint32_t aLoBase = aHiBase + APLANE;
    // B (x4 non-trans of [oc][ic] rows): {b0,b1} oc-octet0, {b0,b1} oc-octet1
    uint32_t wBase = sb + OFF_W
                   + (uint32_t)((lane & 7) + ((lane >> 4) << 3)) * 32
                   + (uint32_t)((lane >> 3) & 1) * 16;

    // ---- main loop: 23 chunks of M=96 (6 m16 tiles), warp-strided ---------
    #pragma unroll 1
    for (int p = wid; p < 23; p += 12) {
        int q0 = p * 96;
        float c[6][4][4];
        #pragma unroll
        for (int mi = 0; mi < 6; mi++)
            #pragma unroll
            for (int j = 0; j < 4; j++)
                #pragma unroll
                for (int r = 0; r < 4; r++) c[mi][j][r] = 0.f;

        uint32_t ah = aHiBase + (uint32_t)q0 * 32;
        uint32_t al = aLoBase + (uint32_t)q0 * 32;

        #pragma unroll
        for (int ky = 0; ky < 5; ky++) {
            #pragma unroll
            for (int kx = 0; kx < 5; kx++) {
                int k = ky * 5 + kx;
                uint32_t off = (uint32_t)(ky * PW_ + kx) * 32;
                uint32_t bh[2][4], bl[2][4];
                uint32_t wtap = wBase + (uint32_t)k * 1024;
                ldsm4(bh[0], wtap);
                ldsm4(bh[1], wtap + 512);
                ldsm4(bl[0], wtap + 25600);
                ldsm4(bl[1], wtap + 25600 + 512);
                #pragma unroll
                for (int mi = 0; mi < 6; mi++) {
                    uint32_t ahi[4], alo[4];
                    ldsm4(ahi, ah + off + (uint32_t)mi * 512);
                    ldsm4(alo, al + off + (uint32_t)mi * 512);
                    #pragma unroll
                    for (int oh = 0; oh < 2; oh++) {
                        // pass 1: ahi*bhi ; pass 2: alo*bhi ; pass 3: ahi*blo
                        mma16816(c[mi][oh * 2 + 0], ahi, bh[oh] + 0);
                        mma16816(c[mi][oh * 2 + 1], ahi, bh[oh] + 2);
                        mma16816(c[mi][oh * 2 + 0], alo, bh[oh] + 0);
                        mma16816(c[mi][oh * 2 + 1], alo, bh[oh] + 2);
                        mma16816(c[mi][oh * 2 + 0], ahi, bl[oh] + 0);
                        mma16816(c[mi][oh * 2 + 1], ahi, bl[oh] + 2);
                    }
                }
            }
        }

        // ---- epilogue: bias+relu+proj, quad-reduce, store -----------------
        #pragma unroll
        for (int mi = 0; mi < 6; mi++) {
            #pragma unroll
            for (int half = 0; half < 2; half++) {
                int row = (lane >> 2) + half * 8;
                int q = q0 + mi * 16 + row;
                int y = q / PW_;
                int xe = q - y * PW_;
                bool valid = (xe >= 2 && xe < 66 && y < 32);
                int px = y * 64 + (xe - 2);
                float v[8];
                #pragma unroll
                for (int n = 0; n < 8; n++) v[n] = 0.f;
                if (valid && !sMask[px]) {
                    #pragma unroll
                    for (int j = 0; j < 4; j++) {
                        #pragma unroll
                        for (int e = 0; e < 2; e++) {
                            int oc = 8 * j + (lane & 3) * 2 + e;
                            float rv = fmaxf(c[mi][j][half * 2 + e] + sBias[oc],
                                             0.f);
                            const float* pt = sProjT + oc * 8;
                            #pragma unroll
                            for (int n = 0; n < 8; n++)
                                v[n] = fmaf(pt[n], rv, v[n]);
                        }
                    }
                }
                #pragma unroll
                for (int n = 0; n < 8; n++) {
                    v[n] += __shfl_xor_sync(0xffffffffu, v[n], 1);
                    v[n] += __shfl_xor_sync(0xffffffffu, v[n], 2);
                }
                if (valid) {
                    int n0 = (lane & 3) * 2;
                    size_t o0 = (((size_t)(b * 8 + n0) * T_ + t) << 11) + px;
                    out[o0] = v[n0];
                    out[o0 + ((size_t)T_ << 11)] = v[n0 + 1];
                }
            }
        }
    }
}

// ---------------------------------------------------------------------------
// K2b: per-channel sum/sumsq over stored pre-BN output (masked entries are 0)
// ---------------------------------------------------------------------------
__global__ void sum_kernel(const float* __restrict__ out) {
    __shared__ float sred[2];
    int tid = threadIdx.x;
    int bk  = blockIdx.x;
    int n   = (bk >> 4) & 7;
    if (tid == 0) { sred[0] = 0.f; sred[1] = 0.f; }
    __syncthreads();
    const float4* p = reinterpret_cast<const float4*>(out) + (size_t)bk * 4096;
    float s = 0.f, sq = 0.f;
    for (int i = tid; i < 4096; i += 256) {
        float4 v = p[i];
        s  += v.x + v.y + v.z + v.w;
        sq += v.x * v.x + v.y * v.y + v.z * v.z + v.w * v.w;
    }
    #pragma unroll
    for (int off = 16; off; off >>= 1) {
        s  += __shfl_xor_sync(0xffffffffu, s, off);
        sq += __shfl_xor_sync(0xffffffffu, sq, off);
    }
    if ((tid & 31) == 0) {
        atomicAdd(&sred[0], s);
        atomicAdd(&sred[1], sq);
    }
    __syncthreads();
    if (tid == 0) {
        atomicAdd(&g_acc[n], sred[0]);
        atomicAdd(&g_acc[8 + n], sred[1]);
    }
}

// ---------------------------------------------------------------------------
// K3 stats
// ---------------------------------------------------------------------------
__global__ void stats_kernel(const float* __restrict__ gamma,
                             const float* __restrict__ beta) {
    int n = threadIdx.x;
    if (n < 8) {
        float cnt  = g_cnt;
        float mean = g_acc[n] / cnt;
        float var  = g_acc[8 + n] / cnt - mean * mean;
        var = fmaxf(var, 0.0f);
        float inv = rsqrtf(var + 1e-5f);
        float sc  = gamma[n] * inv;
        g_scale[n] = sc;
        g_shift[n] = beta[n] - mean * sc;
    }
}

// ---------------------------------------------------------------------------
// K4 BN apply
// ---------------------------------------------------------------------------
__global__ void bn_apply_kernel(float* __restrict__ out,
                                const int* __restrict__ mask) {
    int idx = blockIdx.x * 256 + threadIdx.x;
    int nlin = idx >> 16;
    int n = nlin & 7;
    int bb = nlin >> 3;
    int l4 = idx & 511;
    int4 m = *reinterpret_cast<const int4*>(mask + bb * L_ + l4 * 4);
    float4* p = reinterpret_cast<float4*>(out) + idx;
    float4 v = *p;
    float sc = g_scale[n], sh = g_shift[n];
    v.x = m.x ? v.x : fmaf(v.x, sc, sh);
    v.y = m.y ? v.y : fmaf(v.y, sc, sh);
    v.z = m.z ? v.z : fmaf(v.z, sc, sh);
    v.w = m.w ? v.w : fmaf(v.w, sc, sh);
    *p = v;
}

// ---------------------------------------------------------------------------
extern "C" void kernel_launch(void* const* d_in, const int* in_sizes, int n_in,
                              void* d_out, int out_size) {
    const float* prev  = (const float*)d_in[0];
    const float* curr  = (const float*)d_in[1];
    const int*   mask  = (const int*)d_in[2];
    const float* convw = (const float*)d_in[4];
    const float* convb = (const float*)d_in[5];
    const float* projw = (const float*)d_in[6];
    const float* gamma = (const float*)d_in[7];
    const float* beta  = (const float*)d_in[8];
    float* out = (float*)d_out;

    cudaFuncSetAttribute(conv_kernel,
                         cudaFuncAttributeMaxDynamicSharedMemorySize,
                         SMEM_TOTAL);

    prep_kernel<<<1, 256>>>(mask);
    wprep_kernel<<<25, 512>>>(convw);
    cumsum_kernel<<<256, 256>>>(prev, curr);
    conv_kernel<<<B_ * T_, 384, SMEM_TOTAL>>>(convb, projw, mask, out);
    sum_kernel<<<1024, 256>>>(out);
    stats_kernel<<<1, 32>>>(gamma, beta);
    bn_apply_kernel<<<(B_ * NH_ * T_ * L_ / 4) / 256, 256>>>(out, mask);
}